// round 10
// baseline (speedup 1.0000x reference)
#include <cuda_runtime.h>
#include <cuda_bf16.h>
#include <math.h>

#define BB 32
#define TT 256
#define AA 22
#define FIN 16
#define CC 128
#define HC 512
#define HID 256
#define G4 1024
#define NF (BB*TT)        // 8192 frames

// ---------------- device scratch (static allocations only) ----------------
__device__ float g_pooled[NF*CC];          // 4 MB
__device__ float g_xg[NF*G4];              // 32 MB (layer-0 input transform)
__device__ float g_hlast[BB*HID];

// dtype-robust seq_length read (JAX x64-off => int32 even though ref says int64)
__device__ __forceinline__ int read_len(const int* p, int b)
{
    bool is64 = (p[1] == 0) && (p[3] == 0);
    return is64 ? p[2*b] : p[b];
}

__device__ __forceinline__ float sigmoidf_(float x) { return 1.f/(1.f + expf(-x)); }

// ---------------- packed f32x2 FMA helpers (sm_103a) ----------------------
__device__ __forceinline__ unsigned long long f2pack(float x, float y)
{
    unsigned long long r;
    asm("mov.b64 %0, {%1, %2};" : "=l"(r) : "f"(x), "f"(y));
    return r;
}
__device__ __forceinline__ void f2fma(unsigned long long& d,
                                      unsigned long long a, unsigned long long b)
{
    asm("fma.rn.f32x2 %0, %1, %2, %0;" : "+l"(d) : "l"(a), "l"(b));
}
__device__ __forceinline__ float f2sum(unsigned long long v)
{
    float x, y;
    asm("mov.b64 {%0, %1}, %2;" : "=f"(x), "=f"(y) : "l"(v));
    return x + y;
}
__device__ __forceinline__ void f2unpack(unsigned long long v, float& x, float& y)
{
    asm("mov.b64 {%0, %1}, %2;" : "=f"(x), "=f"(y) : "l"(v));
}

__device__ __forceinline__ unsigned smem_u32(const void* p)
{
    unsigned a;
    asm("{ .reg .u64 t; cvta.to.shared.u64 t, %1; cvt.u32.u64 %0, t; }"
        : "=r"(a) : "l"(p));
    return a;
}
__device__ __forceinline__ void st_cluster_f32(unsigned local_addr, unsigned rank, float v)
{
    unsigned remote;
    asm volatile("mapa.shared::cluster.u32 %0, %1, %2;"
                 : "=r"(remote) : "r"(local_addr), "r"(rank));
    asm volatile("st.shared::cluster.f32 [%0], %1;"
                 :: "r"(remote), "f"(v) : "memory");
}
__device__ __forceinline__ void cluster_sync_()
{
    asm volatile("barrier.cluster.arrive.aligned;" ::: "memory");
    asm volatile("barrier.cluster.wait.aligned;"   ::: "memory");
}

// ---------------- fused GAT (both layers + pool), one block per frame -----
#define OFF_XS     0          // 352
#define OFF_H1     352        // 11264 (reused as x1 after relu)
#define OFF_ASRC   11616      // 88
#define OFF_ADST   11704      // 88
#define OFF_ALPHA1 11792      // 1936
#define OFF_H2     13728      // 2816
#define OFF_A2S    16544      // 22
#define OFF_A2D    16566      // 22
#define OFF_ALPHA2 16588      // 484
#define OFF_PSUM   17072      // 256
#define GAT_SMEM_FLOATS 17328
#define GAT_SMEM_BYTES (GAT_SMEM_FLOATS*4)

extern "C" __global__ void __launch_bounds__(256, 3)
gat_kernel(const float* __restrict__ feat,
           const float* __restrict__ W1, const float* __restrict__ aS1,
           const float* __restrict__ aD1, const float* __restrict__ b1,
           const float* __restrict__ W2, const float* __restrict__ aS2,
           const float* __restrict__ aD2, const float* __restrict__ b2,
           float* __restrict__ pooled)
{
    extern __shared__ float sm[];
    float* xs     = sm + OFF_XS;
    float* h1     = sm + OFF_H1;    // later x1
    float* asrc   = sm + OFF_ASRC;
    float* adst   = sm + OFF_ADST;
    float* alpha1 = sm + OFF_ALPHA1;
    float* h2     = sm + OFF_H2;
    float* a2s    = sm + OFF_A2S;
    float* a2d    = sm + OFF_A2D;
    float* alpha2 = sm + OFF_ALPHA2;
    float* psum   = sm + OFF_PSUM;

    const int n   = blockIdx.x;
    const int tid = threadIdx.x;

    float4* h1_4 = (float4*)h1;
    const float4* W1_4 = (const float4*)W1;
    const float4* b1_4 = (const float4*)b1;

    {
        const float* xgm = feat + (long)n * (AA*FIN);
        for (int i = tid; i < AA*FIN; i += 256) xs[i] = xgm[i];
    }
    __syncthreads();

    // h1[a][hc] = x @ W1
    #pragma unroll
    for (int s = 0; s < 11; s++) {
        int o4 = tid + s*256;
        int a = o4 >> 7, c4 = o4 & 127;
        float4 acc = {0.f,0.f,0.f,0.f};
        #pragma unroll
        for (int f = 0; f < FIN; f++) {
            float xv = xs[a*FIN + f];
            float4 w = W1_4[f*128 + c4];
            acc.x += xv*w.x; acc.y += xv*w.y; acc.z += xv*w.z; acc.w += xv*w.w;
        }
        h1_4[o4] = acc;
    }
    __syncthreads();

    if (tid < 176) {
        int p = tid; bool dst = (p >= 88); if (dst) p -= 88;
        int a = p >> 2, hd = p & 3;
        const float4* att4 = (const float4*)(dst ? aD1 : aS1);
        float a0=0.f,a1=0.f,a2=0.f,a3=0.f;
        #pragma unroll 8
        for (int q = 0; q < 32; q++) {
            float4 h = h1_4[a*128 + hd*32 + q];
            float4 w = att4[hd*32 + q];
            a0 += h.x*w.x; a1 += h.y*w.y; a2 += h.z*w.z; a3 += h.w*w.w;
        }
        (dst ? adst : asrc)[a*4 + hd] = (a0+a1)+(a2+a3);
    }
    __syncthreads();

    if (tid < 88) {
        int i = tid >> 2, hd = tid & 3;
        float di = adst[i*4 + hd];
        float e[AA]; float m = -1e30f;
        #pragma unroll
        for (int j = 0; j < AA; j++) {
            float v = di + asrc[j*4 + hd];
            v = (v > 0.f) ? v : 0.2f*v;
            e[j] = v; m = fmaxf(m, v);
        }
        float ssum = 0.f;
        #pragma unroll
        for (int j = 0; j < AA; j++) { float ex = __expf(e[j]-m); e[j] = ex; ssum += ex; }
        float inv = 1.f/ssum;
        #pragma unroll
        for (int j = 0; j < AA; j++) alpha1[(i*AA+j)*4 + hd] = e[j]*inv;
    }
    __syncthreads();

    // out1 = alpha1 @ h1 (f32x2)
    unsigned long long o01[11], o23[11];
    #pragma unroll
    for (int s = 0; s < 11; s++) { o01[s] = 0ull; o23[s] = 0ull; }
    #pragma unroll
    for (int s = 0; s < 11; s++) {
        int o4 = tid + s*256;
        int a = o4 >> 7, c4 = o4 & 127, hd = c4 >> 5;
        #pragma unroll
        for (int j = 0; j < AA; j++) {
            float al = alpha1[(a*AA+j)*4 + hd];
            unsigned long long aa = f2pack(al, al);
            ulonglong2 hv = *(const ulonglong2*)&h1_4[j*128 + c4];
            f2fma(o01[s], hv.x, aa);
            f2fma(o23[s], hv.y, aa);
        }
    }
    __syncthreads();
    #pragma unroll
    for (int s = 0; s < 11; s++) {
        int o4 = tid + s*256;
        int c4 = o4 & 127;
        float4 bv = b1_4[c4];
        float vx, vy, vz, vw;
        f2unpack(o01[s], vx, vy);
        f2unpack(o23[s], vz, vw);
        float4 v;
        v.x = fmaxf(vx + bv.x, 0.f);
        v.y = fmaxf(vy + bv.y, 0.f);
        v.z = fmaxf(vz + bv.z, 0.f);
        v.w = fmaxf(vw + bv.w, 0.f);
        h1_4[o4] = v;
    }
    __syncthreads();

    // h2 = x1 @ W2 (f32x2)
    {
        int c = tid & 127, ih = tid >> 7;
        int i0 = ih * 11;
        unsigned long long acc2[11];
        #pragma unroll
        for (int ii = 0; ii < 11; ii++) acc2[ii] = 0ull;
        for (int k4 = 0; k4 < 128; k4++) {
            int k = k4*4;
            float w0 = W2[(k+0)*CC + c];
            float w1 = W2[(k+1)*CC + c];
            float w2 = W2[(k+2)*CC + c];
            float w3 = W2[(k+3)*CC + c];
            unsigned long long w01 = f2pack(w0, w1);
            unsigned long long w23 = f2pack(w2, w3);
            #pragma unroll
            for (int ii = 0; ii < 11; ii++) {
                ulonglong2 xv = *(const ulonglong2*)&h1_4[(i0+ii)*128 + k4];
                f2fma(acc2[ii], xv.x, w01);
                f2fma(acc2[ii], xv.y, w23);
            }
        }
        #pragma unroll
        for (int ii = 0; ii < 11; ii++) h2[(i0+ii)*CC + c] = f2sum(acc2[ii]);
    }
    __syncthreads();

    if (tid < 44) {
        int i = tid % AA; bool dst = (tid >= AA);
        const float4* att4 = (const float4*)(dst ? aD2 : aS2);
        const float4* h2_4 = (const float4*)h2;
        float a0=0.f,a1=0.f,a2=0.f,a3=0.f;
        #pragma unroll 8
        for (int q = 0; q < 32; q++) {
            float4 h = h2_4[i*32 + q];
            float4 w = att4[q];
            a0 += h.x*w.x; a1 += h.y*w.y; a2 += h.z*w.z; a3 += h.w*w.w;
        }
        (dst ? a2d : a2s)[i] = (a0+a1)+(a2+a3);
    }
    __syncthreads();
    if (tid < AA) {
        int i = tid;
        float di = a2d[i];
        float e[AA]; float m = -1e30f;
        #pragma unroll
        for (int j = 0; j < AA; j++) {
            float v = di + a2s[j];
            v = (v > 0.f) ? v : 0.2f*v;
            e[j] = v; m = fmaxf(m, v);
        }
        float ssum = 0.f;
        #pragma unroll
        for (int j = 0; j < AA; j++) { float ex = __expf(e[j]-m); e[j] = ex; ssum += ex; }
        float inv = 1.f/ssum;
        #pragma unroll
        for (int j = 0; j < AA; j++) alpha2[i*AA+j] = e[j]*inv;
    }
    __syncthreads();

    {
        int c = tid & 127, ih = tid >> 7;
        float bc = b2[c];
        float s = 0.f;
        for (int i = ih*11; i < ih*11 + 11; i++) {
            float acc = bc;
            #pragma unroll
            for (int j = 0; j < AA; j++) acc += alpha2[i*AA+j] * h2[j*CC + c];
            s += fmaxf(acc, 0.f);
        }
        psum[ih*128 + c] = s;
    }
    __syncthreads();
    if (tid < CC)
        pooled[(long)n*CC + tid] = (psum[tid] + psum[128 + tid]) * (1.f/22.f);
}

// ---------------- input GEMM: out[n][j] = X[n]·W[j] + bi[j] + bh[j] --------
extern "C" __global__ void __launch_bounds__(256)
gemm_xg(const float* __restrict__ X, const float* __restrict__ W,
        const float* __restrict__ bi, const float* __restrict__ bh,
        float* __restrict__ out, int K)
{
    __shared__ float xsm[16*256];
    const int n0 = blockIdx.x * 16;
    const int tid = threadIdx.x;
    for (int idx = tid; idx < 16*K; idx += 256) xsm[idx] = X[(long)n0*K + idx];
    __syncthreads();

    float acc[16][4];
    #pragma unroll
    for (int nn = 0; nn < 16; nn++)
        #pragma unroll
        for (int m = 0; m < 4; m++) acc[nn][m] = 0.f;

    const int r0 = tid, r1 = tid+256, r2 = tid+512, r3 = tid+768;
    for (int k = 0; k < K; k += 4) {
        float4 w0 = *(const float4*)&W[(long)r0*K + k];
        float4 w1 = *(const float4*)&W[(long)r1*K + k];
        float4 w2 = *(const float4*)&W[(long)r2*K + k];
        float4 w3 = *(const float4*)&W[(long)r3*K + k];
        #pragma unroll
        for (int nn = 0; nn < 16; nn++) {
            float4 xv = *(const float4*)&xsm[nn*K + k];
            acc[nn][0] += xv.x*w0.x + xv.y*w0.y + xv.z*w0.z + xv.w*w0.w;
            acc[nn][1] += xv.x*w1.x + xv.y*w1.y + xv.z*w1.z + xv.w*w1.w;
            acc[nn][2] += xv.x*w2.x + xv.y*w2.y + xv.z*w2.z + xv.w*w2.w;
            acc[nn][3] += xv.x*w3.x + xv.y*w3.y + xv.z*w3.z + xv.w*w3.w;
        }
    }
    float bsum0 = bi[r0]+bh[r0], bsum1 = bi[r1]+bh[r1], bsum2 = bi[r2]+bh[r2], bsum3 = bi[r3]+bh[r3];
    #pragma unroll
    for (int nn = 0; nn < 16; nn++) {
        long base = (long)(n0+nn)*G4;
        out[base + r0] = acc[nn][0] + bsum0;
        out[base + r1] = acc[nn][1] + bsum1;
        out[base + r2] = acc[nn][2] + bsum2;
        out[base + r3] = acc[nn][3] + bsum3;
    }
}

// ---------------- cluster-parallel 2-layer pipelined LSTM ------------------
// 8 clusters x 16 CTAs; cluster c owns batches 4c..4c+3.
// CTA rank rk owns units rk*16..rk*16+15 of BOTH layers.
// Dot mapping: thread = (row lr, k-quarter seg); each weight segment is read
// ONCE per round and reused for all 4 batches (4x less smem traffic than the
// (row,batch) mapping). Partials reduced via smem, then nonlinearity + DSMEM.
#define CLN 16
// smem layout (floats)
#define LOFF_WS0 0            // 64 x 260  = 16640
#define LOFF_WS1 16640        // 64 x 524  = 33536
#define LOFF_H0B 50176        // 2 x 4 x 260 = 2080
#define LOFF_H1B 52256        // 2 x 4 x 260 = 2080
#define LOFF_PS0 54336        // 4 x 4 x 64 = 1024
#define LOFF_PS1 55360        // 1024
#define LOFF_GS0 56384        // 256
#define LOFF_GS1 56640        // 256
#define LOFF_B1S 56896        // 64
#define LSTM_SMEM_FLOATS 56960
#define LSTM_SMEM_BYTES (LSTM_SMEM_FLOATS*4)   // 227840

extern "C" __global__ void __launch_bounds__(256)
__cluster_dims__(CLN, 1, 1)
lstm_cluster(const float* __restrict__ xg0,
             const float* __restrict__ Whh0,
             const float* __restrict__ Wih1, const float* __restrict__ Whh1,
             const float* __restrict__ bih1, const float* __restrict__ bhh1,
             const int* __restrict__ slen,
             float* __restrict__ hlast)
{
    extern __shared__ float smf[];
    float* ws0 = smf + LOFF_WS0;
    float* ws1 = smf + LOFF_WS1;
    float* h0b = smf + LOFF_H0B;
    float* h1b = smf + LOFF_H1B;
    float* ps0 = smf + LOFF_PS0;
    float* ps1 = smf + LOFF_PS1;
    float* gs0 = smf + LOFF_GS0;
    float* gs1 = smf + LOFF_GS1;
    float* b1s = smf + LOFF_B1S;

    const int tid = threadIdx.x;
    const int cl  = blockIdx.x >> 4;     // cluster id (batch group)
    const int rk  = blockIdx.x & 15;     // rank in cluster (unit group)

    // ---- init: load weight slices ----
    for (int idx = tid; idx < 64*256; idx += 256) {
        int lw = idx >> 8, k = idx & 255;
        int j = (lw >> 4)*256 + rk*16 + (lw & 15);
        ws0[lw*260 + k] = Whh0[j*256 + k];
    }
    for (int idx = tid; idx < 64*512; idx += 256) {
        int lw = idx >> 9, k = idx & 511;
        int j = (lw >> 4)*256 + rk*16 + (lw & 15);
        ws1[lw*524 + k] = (k < 256) ? Wih1[j*256 + k] : Whh1[j*256 + (k-256)];
    }
    if (tid < 64) {
        int j = (tid >> 4)*256 + rk*16 + (tid & 15);
        b1s[tid] = bih1[j] + bhh1[j];
    }
    // zero h buffers (both parities, incl pad)
    for (int idx = tid; idx < 2*4*260; idx += 256) { h0b[idx] = 0.f; h1b[idx] = 0.f; }

    // dot-task mapping: tid = lr*4 + seg   (row lr 0..63, k-quarter seg 0..3)
    const int lr  = tid >> 2, seg = tid & 3;
    // reduce mapping: tid = rb*64 + rl  (batch rb 0..3, row rl 0..63)
    const int rb = tid >> 6, rl = tid & 63;
    const int jr = (rl >> 4)*256 + rk*16 + (rl & 15);   // global gate row for (rl)
    const int bgr = cl*4 + rb;
    // nonlinearity mapping: tid<64 -> L0; tid in [64,128) -> L1
    const int nb = (tid < 64) ? (tid >> 4) : ((tid - 64) >> 4);
    const int nu = (tid < 64) ? (tid & 15) : ((tid - 64) & 15);
    const int nlen = read_len(slen, cl*4 + nb);
    const int uglob = rk*16 + nu;
    float creg = 0.f;

    const float4* ws0_4 = (const float4*)ws0;
    const float4* ws1_4 = (const float4*)ws1;

    float xn = xg0[(long)(bgr*TT + 0)*G4 + jr];   // reducer's round-0 x-gate

    cluster_sync_();   // weights + zeroed h visible cluster-wide

    for (int r = 0; r <= TT; r++) {
        const int rp = (r + 1) & 1;   // read parity (h[r-1])
        const int wp = r & 1;         // write parity (h[r])

        // ---- L0 partial dot: rows lr, k in [seg*64, seg*64+64), all 4 batches
        if (r < TT) {
            const float4* h0r = (const float4*)(h0b + rp*1040);   // [b][65] f4
            unsigned long long A0[4] = {0ull,0ull,0ull,0ull};
            unsigned long long A1[4] = {0ull,0ull,0ull,0ull};
            #pragma unroll 4
            for (int k4 = 0; k4 < 16; k4++) {
                ulonglong2 w = *(const ulonglong2*)&ws0_4[lr*65 + seg*16 + k4];
                #pragma unroll
                for (int b = 0; b < 4; b++) {
                    ulonglong2 h = *(const ulonglong2*)&h0r[b*65 + seg*16 + k4];
                    f2fma(A0[b], h.x, w.x);
                    f2fma(A1[b], h.y, w.y);
                }
            }
            #pragma unroll
            for (int b = 0; b < 4; b++)
                ps0[seg*256 + b*64 + lr] = f2sum(A0[b]) + f2sum(A1[b]);
        }

        // ---- L1 partial dot: k in [seg*128, seg*128+128) of [h0 | h1]
        if (r >= 1) {
            const float4* hs4 = (const float4*)((seg < 2 ? h0b : h1b) + rp*1040);
            const int o4 = (seg & 1)*32;
            unsigned long long A0[4] = {0ull,0ull,0ull,0ull};
            unsigned long long A1[4] = {0ull,0ull,0ull,0ull};
            #pragma unroll 4
            for (int k4 = 0; k4 < 32; k4++) {
                ulonglong2 w = *(const ulonglong2*)&ws1_4[lr*131 + seg*32 + k4];
                #pragma unroll
                for (int b = 0; b < 4; b++) {
                    ulonglong2 h = *(const ulonglong2*)&hs4[b*65 + o4 + k4];
                    f2fma(A0[b], h.x, w.x);
                    f2fma(A1[b], h.y, w.y);
                }
            }
            #pragma unroll
            for (int b = 0; b < 4; b++)
                ps1[seg*256 + b*64 + lr] = f2sum(A0[b]) + f2sum(A1[b]);
        }
        __syncthreads();

        // ---- reduce partials -> gate values ----
        if (r < TT) {
            gs0[tid] = ps0[tid] + ps0[256 + tid] + ps0[512 + tid] + ps0[768 + tid] + xn;
            if (r + 1 < TT) xn = xg0[(long)(bgr*TT + (r+1))*G4 + jr];
        }
        if (r >= 1) {
            gs1[tid] = ps1[tid] + ps1[256 + tid] + ps1[512 + tid] + ps1[768 + tid] + b1s[rl];
        }
        __syncthreads();

        // ---- nonlinearity + DSMEM broadcast ----
        if (tid < 64 && r < TT) {
            float gi = sigmoidf_(gs0[nb*64 +  0 + nu]);
            float gf = sigmoidf_(gs0[nb*64 + 16 + nu]);
            float gg = tanhf    (gs0[nb*64 + 32 + nu]);
            float go = sigmoidf_(gs0[nb*64 + 48 + nu]);
            float cn = gf*creg + gi*gg;
            float hn = go * tanhf(cn);
            if (r >= nlen) { cn = creg; hn = h0b[rp*1040 + nb*260 + uglob]; }
            creg = cn;
            unsigned la = smem_u32(&h0b[wp*1040 + nb*260 + uglob]);
            #pragma unroll
            for (int d = 0; d < CLN; d++) st_cluster_f32(la, d, hn);
        } else if (tid >= 64 && tid < 128 && r >= 1) {
            const int s = r - 1;
            float gi = sigmoidf_(gs1[nb*64 +  0 + nu]);
            float gf = sigmoidf_(gs1[nb*64 + 16 + nu]);
            float gg = tanhf    (gs1[nb*64 + 32 + nu]);
            float go = sigmoidf_(gs1[nb*64 + 48 + nu]);
            float cn = gf*creg + gi*gg;
            float hn = go * tanhf(cn);
            if (s >= nlen) { cn = creg; hn = h1b[rp*1040 + nb*260 + uglob]; }
            creg = cn;
            if (s < TT-1) {
                unsigned la = smem_u32(&h1b[wp*1040 + nb*260 + uglob]);
                #pragma unroll
                for (int d = 0; d < CLN; d++) st_cluster_f32(la, d, hn);
            } else {
                hlast[(cl*4 + nb)*HID + uglob] = hn;
            }
        }

        if (r < TT) cluster_sync_();
    }

    // final safety: no CTA exits while any peer-smem op could be in flight
    cluster_sync_();
}

extern "C" __global__ void final_kernel(const float* __restrict__ hlast,
                                        const float* __restrict__ w,
                                        const float* __restrict__ bias,
                                        float* __restrict__ out)
{
    int b = threadIdx.x;
    if (b < BB) {
        float s = bias[0];
        for (int k = 0; k < HID; k++) s += hlast[b*HID + k] * w[k];
        out[b] = s;
    }
}

// ---------------- launch ----------------
extern "C" void kernel_launch(void* const* d_in, const int* in_sizes, int n_in,
                              void* d_out, int out_size)
{
    const float* feat = (const float*)d_in[0];
    const int*   slen = (const int*)d_in[1];
    const float* W1   = (const float*)d_in[2];
    const float* aS1  = (const float*)d_in[3];
    const float* aD1  = (const float*)d_in[4];
    const float* b1   = (const float*)d_in[5];
    const float* W2   = (const float*)d_in[6];
    const float* aS2  = (const float*)d_in[7];
    const float* aD2  = (const float*)d_in[8];
    const float* b2   = (const float*)d_in[9];
    const float* Wih0 = (const float*)d_in[10];
    const float* Whh0 = (const float*)d_in[11];
    const float* bih0 = (const float*)d_in[12];
    const float* bhh0 = (const float*)d_in[13];
    const float* Wih1 = (const float*)d_in[14];
    const float* Whh1 = (const float*)d_in[15];
    const float* bih1 = (const float*)d_in[16];
    const float* bhh1 = (const float*)d_in[17];
    const float* clfw = (const float*)d_in[18];
    const float* clfb = (const float*)d_in[19];
    float* out = (float*)d_out;

    cudaFuncSetAttribute(gat_kernel,   cudaFuncAttributeMaxDynamicSharedMemorySize, GAT_SMEM_BYTES);
    cudaFuncSetAttribute(lstm_cluster, cudaFuncAttributeMaxDynamicSharedMemorySize, LSTM_SMEM_BYTES);
    cudaFuncSetAttribute(lstm_cluster, cudaFuncAttributeNonPortableClusterSizeAllowed, 1);

    float* pooled; cudaGetSymbolAddress((void**)&pooled, g_pooled);
    float* xg;     cudaGetSymbolAddress((void**)&xg,     g_xg);
    float* hlast;  cudaGetSymbolAddress((void**)&hlast,  g_hlast);

    // 1) fused GAT + pooling over all 8192 frames
    gat_kernel<<<NF, 256, GAT_SMEM_BYTES>>>(feat, W1, aS1, aD1, b1, W2, aS2, aD2, b2, pooled);

    // 2) layer-0 input transform: xg = pooled @ Wih0^T + bih0 + bhh0
    gemm_xg<<<NF/16, 256>>>(pooled, Wih0, bih0, bhh0, xg, CC);

    // 3) cluster-parallel fused 2-layer recurrence (redundancy-free weight reads)
    lstm_cluster<<<128, 256, LSTM_SMEM_BYTES>>>(xg, Whh0, Wih1, Whh1, bih1, bhh1,
                                                slen, hlast);

    // 4) classifier
    final_kernel<<<1, 32>>>(hlast, clfw, clfb, out);
}

// round 12
// speedup vs baseline: 1.9223x; 1.9223x over previous
#include <cuda_runtime.h>
#include <cuda_bf16.h>
#include <math.h>

#define BB 32
#define TT 256
#define AA 22
#define FIN 16
#define CC 128
#define HC 512
#define HID 256
#define G4 1024
#define NF (BB*TT)        // 8192 frames
#define LSTM_BLOCKS 128

// ---------------- device scratch (static allocations only) ----------------
__device__ float g_pooled[NF*CC];          // 4 MB
__device__ float g_xg[NF*G4];              // 32 MB (layer-0 input transform)
__device__ float g_h0buf[2*BB*HID];        // h0 double buffer
__device__ float g_h1buf[2*BB*HID];        // h1 double buffer
__device__ float g_hlast[BB*HID];
__device__ unsigned g_bar_count;
__device__ volatile unsigned g_bar_epoch;

// dtype-robust seq_length read (JAX x64-off => int32 even though ref says int64)
__device__ __forceinline__ int read_len(const int* p, int b)
{
    bool is64 = (p[1] == 0) && (p[3] == 0);
    return is64 ? p[2*b] : p[b];
}

__device__ __forceinline__ float sigmoidf_(float x) { return 1.f/(1.f + expf(-x)); }

// ---------------- packed f32x2 FMA helpers (sm_103a) ----------------------
__device__ __forceinline__ unsigned long long f2pack(float x, float y)
{
    unsigned long long r;
    asm("mov.b64 %0, {%1, %2};" : "=l"(r) : "f"(x), "f"(y));
    return r;
}
__device__ __forceinline__ void f2fma(unsigned long long& d,
                                      unsigned long long a, unsigned long long b)
{
    asm("fma.rn.f32x2 %0, %1, %2, %0;" : "+l"(d) : "l"(a), "l"(b));
}
__device__ __forceinline__ float f2sum(unsigned long long v)
{
    float x, y;
    asm("mov.b64 {%0, %1}, %2;" : "=f"(x), "=f"(y) : "l"(v));
    return x + y;
}
__device__ __forceinline__ void f2unpack(unsigned long long v, float& x, float& y)
{
    asm("mov.b64 {%0, %1}, %2;" : "=f"(x), "=f"(y) : "l"(v));
}

// ---------------- fused GAT (both layers + pool), one block per frame -----
#define OFF_XS     0          // 352
#define OFF_H1     352        // 11264 (reused as x1 after relu)
#define OFF_ASRC   11616      // 88
#define OFF_ADST   11704      // 88
#define OFF_ALPHA1 11792      // 1936
#define OFF_H2     13728      // 2816
#define OFF_A2S    16544      // 22
#define OFF_A2D    16566      // 22
#define OFF_ALPHA2 16588      // 484
#define OFF_PSUM   17072      // 256
#define GAT_SMEM_FLOATS 17328
#define GAT_SMEM_BYTES (GAT_SMEM_FLOATS*4)

extern "C" __global__ void __launch_bounds__(256, 3)
gat_kernel(const float* __restrict__ feat,
           const float* __restrict__ W1, const float* __restrict__ aS1,
           const float* __restrict__ aD1, const float* __restrict__ b1,
           const float* __restrict__ W2, const float* __restrict__ aS2,
           const float* __restrict__ aD2, const float* __restrict__ b2,
           float* __restrict__ pooled)
{
    extern __shared__ float sm[];
    float* xs     = sm + OFF_XS;
    float* h1     = sm + OFF_H1;    // later x1
    float* asrc   = sm + OFF_ASRC;
    float* adst   = sm + OFF_ADST;
    float* alpha1 = sm + OFF_ALPHA1;
    float* h2     = sm + OFF_H2;
    float* a2s    = sm + OFF_A2S;
    float* a2d    = sm + OFF_A2D;
    float* alpha2 = sm + OFF_ALPHA2;
    float* psum   = sm + OFF_PSUM;

    const int n   = blockIdx.x;
    const int tid = threadIdx.x;

    float4* h1_4 = (float4*)h1;
    const float4* W1_4 = (const float4*)W1;
    const float4* b1_4 = (const float4*)b1;

    {
        const float* xgm = feat + (long)n * (AA*FIN);
        for (int i = tid; i < AA*FIN; i += 256) xs[i] = xgm[i];
    }
    __syncthreads();

    // h1[a][hc] = x @ W1
    #pragma unroll
    for (int s = 0; s < 11; s++) {
        int o4 = tid + s*256;
        int a = o4 >> 7, c4 = o4 & 127;
        float4 acc = {0.f,0.f,0.f,0.f};
        #pragma unroll
        for (int f = 0; f < FIN; f++) {
            float xv = xs[a*FIN + f];
            float4 w = W1_4[f*128 + c4];
            acc.x += xv*w.x; acc.y += xv*w.y; acc.z += xv*w.z; acc.w += xv*w.w;
        }
        h1_4[o4] = acc;
    }
    __syncthreads();

    if (tid < 176) {
        int p = tid; bool dst = (p >= 88); if (dst) p -= 88;
        int a = p >> 2, hd = p & 3;
        const float4* att4 = (const float4*)(dst ? aD1 : aS1);
        float a0=0.f,a1=0.f,a2=0.f,a3=0.f;
        #pragma unroll 8
        for (int q = 0; q < 32; q++) {
            float4 h = h1_4[a*128 + hd*32 + q];
            float4 w = att4[hd*32 + q];
            a0 += h.x*w.x; a1 += h.y*w.y; a2 += h.z*w.z; a3 += h.w*w.w;
        }
        (dst ? adst : asrc)[a*4 + hd] = (a0+a1)+(a2+a3);
    }
    __syncthreads();

    if (tid < 88) {
        int i = tid >> 2, hd = tid & 3;
        float di = adst[i*4 + hd];
        float e[AA]; float m = -1e30f;
        #pragma unroll
        for (int j = 0; j < AA; j++) {
            float v = di + asrc[j*4 + hd];
            v = (v > 0.f) ? v : 0.2f*v;
            e[j] = v; m = fmaxf(m, v);
        }
        float ssum = 0.f;
        #pragma unroll
        for (int j = 0; j < AA; j++) { float ex = __expf(e[j]-m); e[j] = ex; ssum += ex; }
        float inv = 1.f/ssum;
        #pragma unroll
        for (int j = 0; j < AA; j++) alpha1[(i*AA+j)*4 + hd] = e[j]*inv;
    }
    __syncthreads();

    // out1 = alpha1 @ h1 (f32x2)
    unsigned long long o01[11], o23[11];
    #pragma unroll
    for (int s = 0; s < 11; s++) { o01[s] = 0ull; o23[s] = 0ull; }
    #pragma unroll
    for (int s = 0; s < 11; s++) {
        int o4 = tid + s*256;
        int a = o4 >> 7, c4 = o4 & 127, hd = c4 >> 5;
        #pragma unroll
        for (int j = 0; j < AA; j++) {
            float al = alpha1[(a*AA+j)*4 + hd];
            unsigned long long aa = f2pack(al, al);
            ulonglong2 hv = *(const ulonglong2*)&h1_4[j*128 + c4];
            f2fma(o01[s], hv.x, aa);
            f2fma(o23[s], hv.y, aa);
        }
    }
    __syncthreads();
    #pragma unroll
    for (int s = 0; s < 11; s++) {
        int o4 = tid + s*256;
        int c4 = o4 & 127;
        float4 bv = b1_4[c4];
        float vx, vy, vz, vw;
        f2unpack(o01[s], vx, vy);
        f2unpack(o23[s], vz, vw);
        float4 v;
        v.x = fmaxf(vx + bv.x, 0.f);
        v.y = fmaxf(vy + bv.y, 0.f);
        v.z = fmaxf(vz + bv.z, 0.f);
        v.w = fmaxf(vw + bv.w, 0.f);
        h1_4[o4] = v;
    }
    __syncthreads();

    // h2 = x1 @ W2 (f32x2)
    {
        int c = tid & 127, ih = tid >> 7;
        int i0 = ih * 11;
        unsigned long long acc2[11];
        #pragma unroll
        for (int ii = 0; ii < 11; ii++) acc2[ii] = 0ull;
        for (int k4 = 0; k4 < 128; k4++) {
            int k = k4*4;
            float w0 = W2[(k+0)*CC + c];
            float w1 = W2[(k+1)*CC + c];
            float w2 = W2[(k+2)*CC + c];
            float w3 = W2[(k+3)*CC + c];
            unsigned long long w01 = f2pack(w0, w1);
            unsigned long long w23 = f2pack(w2, w3);
            #pragma unroll
            for (int ii = 0; ii < 11; ii++) {
                ulonglong2 xv = *(const ulonglong2*)&h1_4[(i0+ii)*128 + k4];
                f2fma(acc2[ii], xv.x, w01);
                f2fma(acc2[ii], xv.y, w23);
            }
        }
        #pragma unroll
        for (int ii = 0; ii < 11; ii++) h2[(i0+ii)*CC + c] = f2sum(acc2[ii]);
    }
    __syncthreads();

    if (tid < 44) {
        int i = tid % AA; bool dst = (tid >= AA);
        const float4* att4 = (const float4*)(dst ? aD2 : aS2);
        const float4* h2_4 = (const float4*)h2;
        float a0=0.f,a1=0.f,a2=0.f,a3=0.f;
        #pragma unroll 8
        for (int q = 0; q < 32; q++) {
            float4 h = h2_4[i*32 + q];
            float4 w = att4[q];
            a0 += h.x*w.x; a1 += h.y*w.y; a2 += h.z*w.z; a3 += h.w*w.w;
        }
        (dst ? a2d : a2s)[i] = (a0+a1)+(a2+a3);
    }
    __syncthreads();
    if (tid < AA) {
        int i = tid;
        float di = a2d[i];
        float e[AA]; float m = -1e30f;
        #pragma unroll
        for (int j = 0; j < AA; j++) {
            float v = di + a2s[j];
            v = (v > 0.f) ? v : 0.2f*v;
            e[j] = v; m = fmaxf(m, v);
        }
        float ssum = 0.f;
        #pragma unroll
        for (int j = 0; j < AA; j++) { float ex = __expf(e[j]-m); e[j] = ex; ssum += ex; }
        float inv = 1.f/ssum;
        #pragma unroll
        for (int j = 0; j < AA; j++) alpha2[i*AA+j] = e[j]*inv;
    }
    __syncthreads();

    {
        int c = tid & 127, ih = tid >> 7;
        float bc = b2[c];
        float s = 0.f;
        for (int i = ih*11; i < ih*11 + 11; i++) {
            float acc = bc;
            #pragma unroll
            for (int j = 0; j < AA; j++) acc += alpha2[i*AA+j] * h2[j*CC + c];
            s += fmaxf(acc, 0.f);
        }
        psum[ih*128 + c] = s;
    }
    __syncthreads();
    if (tid < CC)
        pooled[(long)n*CC + tid] = (psum[tid] + psum[128 + tid]) * (1.f/22.f);
}

// ---------------- input GEMM: out[n][j] = X[n]·W[j] + bi[j] + bh[j] --------
extern "C" __global__ void __launch_bounds__(256)
gemm_xg(const float* __restrict__ X, const float* __restrict__ W,
        const float* __restrict__ bi, const float* __restrict__ bh,
        float* __restrict__ out, int K)
{
    __shared__ float xsm[16*256];
    const int n0 = blockIdx.x * 16;
    const int tid = threadIdx.x;
    for (int idx = tid; idx < 16*K; idx += 256) xsm[idx] = X[(long)n0*K + idx];
    __syncthreads();

    float acc[16][4];
    #pragma unroll
    for (int nn = 0; nn < 16; nn++)
        #pragma unroll
        for (int m = 0; m < 4; m++) acc[nn][m] = 0.f;

    const int r0 = tid, r1 = tid+256, r2 = tid+512, r3 = tid+768;
    for (int k = 0; k < K; k += 4) {
        float4 w0 = *(const float4*)&W[(long)r0*K + k];
        float4 w1 = *(const float4*)&W[(long)r1*K + k];
        float4 w2 = *(const float4*)&W[(long)r2*K + k];
        float4 w3 = *(const float4*)&W[(long)r3*K + k];
        #pragma unroll
        for (int nn = 0; nn < 16; nn++) {
            float4 xv = *(const float4*)&xsm[nn*K + k];
            acc[nn][0] += xv.x*w0.x + xv.y*w0.y + xv.z*w0.z + xv.w*w0.w;
            acc[nn][1] += xv.x*w1.x + xv.y*w1.y + xv.z*w1.z + xv.w*w1.w;
            acc[nn][2] += xv.x*w2.x + xv.y*w2.y + xv.z*w2.z + xv.w*w2.w;
            acc[nn][3] += xv.x*w3.x + xv.y*w3.y + xv.z*w3.z + xv.w*w3.w;
        }
    }
    float bsum0 = bi[r0]+bh[r0], bsum1 = bi[r1]+bh[r1], bsum2 = bi[r2]+bh[r2], bsum3 = bi[r3]+bh[r3];
    #pragma unroll
    for (int nn = 0; nn < 16; nn++) {
        long base = (long)(n0+nn)*G4;
        out[base + r0] = acc[nn][0] + bsum0;
        out[base + r1] = acc[nn][1] + bsum1;
        out[base + r2] = acc[nn][2] + bsum2;
        out[base + r3] = acc[nn][3] + bsum3;
    }
}

// ---------------- fused 2-layer LSTM, 128 blocks, global epoch barrier -----
// Block bid owns units {2*bid, 2*bid+1} of BOTH layers (8 gate rows each).
// Thread (b = tid>>3, q = tid&7): one L0 row-dot (len 256) + one L1 row-dot
// (len 512 = [h0 | h1]) per round. Layers pipelined with 1-step skew:
// round r runs L0 step r and L1 step r-1. 257 rounds, 256 barriers.
// smem layout (floats)
#define FOFF_WS0 0            // 8 x 260  = 2080
#define FOFF_WS1 2080         // 8 x 520  = 4160
#define FOFF_H0S 6240         // 32 x 260 = 8320
#define FOFF_H1S 14560        // 32 x 260 = 8320
#define FOFF_GS0 22880        // 32 x 8   = 256
#define FOFF_GS1 23136        // 32 x 8   = 256
#define FOFF_B1S 23392        // 8
#define FUSED_SMEM_FLOATS 23400
#define FUSED_SMEM_BYTES (FUSED_SMEM_FLOATS*4)   // 93600

__device__ __forceinline__ void grid_barrier_epoch(unsigned target)
{
    __threadfence();               // release all threads' prior global writes
    __syncthreads();
    if (threadIdx.x == 0) {
        unsigned prev = atomicAdd(&g_bar_count, 1u);
        if (prev == (unsigned)(LSTM_BLOCKS - 1)) {
            g_bar_count = 0u;
            __threadfence();
            g_bar_epoch = target;
        } else {
            while (g_bar_epoch < target) { }
        }
        __threadfence();
    }
    __syncthreads();
}

extern "C" __global__ void __launch_bounds__(256)
lstm_fused128(const float* __restrict__ xg0,
              const float* __restrict__ Whh0,
              const float* __restrict__ Wih1, const float* __restrict__ Whh1,
              const float* __restrict__ bih1, const float* __restrict__ bhh1,
              const int* __restrict__ slen,
              float* __restrict__ h0buf, float* __restrict__ h1buf,
              float* __restrict__ hlast)
{
    extern __shared__ float smf[];
    float* ws0 = smf + FOFF_WS0;
    float* ws1 = smf + FOFF_WS1;
    float* h0s = smf + FOFF_H0S;
    float* h1s = smf + FOFF_H1S;
    float* gs0 = smf + FOFF_GS0;
    float* gs1 = smf + FOFF_GS1;
    float* b1s = smf + FOFF_B1S;

    const int tid = threadIdx.x;
    const int bid = blockIdx.x;

    // weight slices: row q -> global gate row j = (q>>1)*256 + bid*2 + (q&1)
    for (int idx = tid; idx < 8*256; idx += 256) {
        int q = idx >> 8, k = idx & 255;
        int j = (q >> 1)*256 + bid*2 + (q & 1);
        ws0[q*260 + k] = Whh0[j*256 + k];
    }
    for (int idx = tid; idx < 8*512; idx += 256) {
        int q = idx >> 9, k = idx & 511;
        int j = (q >> 1)*256 + bid*2 + (q & 1);
        ws1[q*520 + k] = (k < 256) ? Wih1[j*256 + k] : Whh1[j*256 + (k-256)];
    }
    if (tid < 8) {
        int j = (tid >> 1)*256 + bid*2 + (tid & 1);
        b1s[tid] = bih1[j] + bhh1[j];
    }

    const int b = tid >> 3, q = tid & 7;
    const int j0 = (q >> 1)*256 + bid*2 + (q & 1);
    const int u  = bid*2 + (q & 1);          // unit for nonlin threads
    const int mylen = read_len(slen, b);
    float creg0 = 0.f, creg1 = 0.f;

    const float4* ws0_4 = (const float4*)ws0;
    const float4* ws1_4 = (const float4*)ws1;
    const float4* h0s_4 = (const float4*)h0s;
    const float4* h1s_4 = (const float4*)h1s;
    const float4* h0g4  = (const float4*)h0buf;
    const float4* h1g4  = (const float4*)h1buf;

    float xn = xg0[(long)(b*TT + 0)*G4 + j0];   // prefetch round-0 x-gate
    __syncthreads();

    for (int r = 0; r <= TT; r++) {
        const int rp = (r + 1) & 1;   // read parity
        const int wp = r & 1;         // write parity

        // stage h0[r-1] and h1[r-2] from parity rp: 2048 f4 each buffer
        for (int idx = tid; idx < 4096; idx += 256) {
            int sel = idx >> 11;             // 0: h0, 1: h1
            int e   = idx & 2047;            // 32 batches x 64 f4
            int bb = e >> 6, ii = e & 63;
            float4 v = sel ? h1g4[rp*2048 + e] : h0g4[rp*2048 + e];
            if (sel) ((float4*)h1s)[bb*65 + ii] = v;
            else     ((float4*)h0s)[bb*65 + ii] = v;
        }
        __syncthreads();

        // ---- L0 dot ----
        if (r < TT) {
            unsigned long long a01 = 0ull, a23 = 0ull;
            #pragma unroll 8
            for (int k4 = 0; k4 < 64; k4++) {
                ulonglong2 h = *(const ulonglong2*)&h0s_4[b*65 + k4];
                ulonglong2 w = *(const ulonglong2*)&ws0_4[q*65 + k4];
                f2fma(a01, h.x, w.x);
                f2fma(a23, h.y, w.y);
            }
            gs0[b*8 + q] = f2sum(a01) + f2sum(a23) + xn;
            if (r + 1 < TT) xn = xg0[(long)(b*TT + (r+1))*G4 + j0];
        }

        // ---- L1 dot: [h0[r-1] | h1[r-2]] ----
        if (r >= 1) {
            unsigned long long a01 = 0ull, a23 = 0ull;
            #pragma unroll 8
            for (int k4 = 0; k4 < 64; k4++) {
                ulonglong2 h = *(const ulonglong2*)&h0s_4[b*65 + k4];
                ulonglong2 w = *(const ulonglong2*)&ws1_4[q*130 + k4];
                f2fma(a01, h.x, w.x);
                f2fma(a23, h.y, w.y);
            }
            #pragma unroll 8
            for (int k4 = 0; k4 < 64; k4++) {
                ulonglong2 h = *(const ulonglong2*)&h1s_4[b*65 + k4];
                ulonglong2 w = *(const ulonglong2*)&ws1_4[q*130 + 64 + k4];
                f2fma(a01, h.x, w.x);
                f2fma(a23, h.y, w.y);
            }
            gs1[b*8 + q] = f2sum(a01) + f2sum(a23) + b1s[q];
        }
        __syncthreads();

        // ---- nonlinearity + state update ----
        if (q < 2 && r < TT) {
            float gi = sigmoidf_(gs0[b*8 + 0 + q]);
            float gf = sigmoidf_(gs0[b*8 + 2 + q]);
            float gg = tanhf    (gs0[b*8 + 4 + q]);
            float go = sigmoidf_(gs0[b*8 + 6 + q]);
            float cn = gf*creg0 + gi*gg;
            float hn = go * tanhf(cn);
            if (r >= mylen) { cn = creg0; hn = h0s[b*260 + u]; }
            creg0 = cn;
            h0buf[wp*BB*HID + b*HID + u] = hn;
        } else if (q >= 2 && q < 4 && r >= 1) {
            const int s = r - 1;
            const int uu = q - 2;
            const int u1 = bid*2 + uu;
            float gi = sigmoidf_(gs1[b*8 + 0 + uu]);
            float gf = sigmoidf_(gs1[b*8 + 2 + uu]);
            float gg = tanhf    (gs1[b*8 + 4 + uu]);
            float go = sigmoidf_(gs1[b*8 + 6 + uu]);
            float cn = gf*creg1 + gi*gg;
            float hn = go * tanhf(cn);
            if (s >= mylen) { cn = creg1; hn = h1s[b*260 + u1]; }
            creg1 = cn;
            h1buf[wp*BB*HID + b*HID + u1] = hn;
            if (s == TT-1) hlast[b*HID + u1] = hn;
        }

        if (r < TT) grid_barrier_epoch(r + 1);
    }
}

extern "C" __global__ void zero_init(float* h0, float* h1)
{
    int i = blockIdx.x*256 + threadIdx.x;
    if (i < 2*BB*HID) { h0[i] = 0.f; h1[i] = 0.f; }
    if (i == 0) { g_bar_count = 0u; g_bar_epoch = 0u; }
}

extern "C" __global__ void final_kernel(const float* __restrict__ hlast,
                                        const float* __restrict__ w,
                                        const float* __restrict__ bias,
                                        float* __restrict__ out)
{
    // 256 threads: 32 batches x 8 lanes; each lane sums 32 strided elems
    const int tid = threadIdx.x;
    const int b = tid >> 3, l = tid & 7;
    float s = 0.f;
    for (int k = l; k < HID; k += 8) s += hlast[b*HID + k] * w[k];
    s += __shfl_xor_sync(0xffffffffu, s, 4);
    s += __shfl_xor_sync(0xffffffffu, s, 2);
    s += __shfl_xor_sync(0xffffffffu, s, 1);
    if (l == 0) out[b] = s + bias[0];
}

// ---------------- launch ----------------
extern "C" void kernel_launch(void* const* d_in, const int* in_sizes, int n_in,
                              void* d_out, int out_size)
{
    const float* feat = (const float*)d_in[0];
    const int*   slen = (const int*)d_in[1];
    const float* W1   = (const float*)d_in[2];
    const float* aS1  = (const float*)d_in[3];
    const float* aD1  = (const float*)d_in[4];
    const float* b1   = (const float*)d_in[5];
    const float* W2   = (const float*)d_in[6];
    const float* aS2  = (const float*)d_in[7];
    const float* aD2  = (const float*)d_in[8];
    const float* b2   = (const float*)d_in[9];
    const float* Wih0 = (const float*)d_in[10];
    const float* Whh0 = (const float*)d_in[11];
    const float* bih0 = (const float*)d_in[12];
    const float* bhh0 = (const float*)d_in[13];
    const float* Wih1 = (const float*)d_in[14];
    const float* Whh1 = (const float*)d_in[15];
    const float* bih1 = (const float*)d_in[16];
    const float* bhh1 = (const float*)d_in[17];
    const float* clfw = (const float*)d_in[18];
    const float* clfb = (const float*)d_in[19];
    float* out = (float*)d_out;

    cudaFuncSetAttribute(gat_kernel,    cudaFuncAttributeMaxDynamicSharedMemorySize, GAT_SMEM_BYTES);
    cudaFuncSetAttribute(lstm_fused128, cudaFuncAttributeMaxDynamicSharedMemorySize, FUSED_SMEM_BYTES);

    float* pooled; cudaGetSymbolAddress((void**)&pooled, g_pooled);
    float* xg;     cudaGetSymbolAddress((void**)&xg,     g_xg);
    float* h0buf;  cudaGetSymbolAddress((void**)&h0buf,  g_h0buf);
    float* h1buf;  cudaGetSymbolAddress((void**)&h1buf,  g_h1buf);
    float* hlast;  cudaGetSymbolAddress((void**)&hlast,  g_hlast);

    // 1) fused GAT + pooling over all 8192 frames
    gat_kernel<<<NF, 256, GAT_SMEM_BYTES>>>(feat, W1, aS1, aD1, b1, W2, aS2, aD2, b2, pooled);

    // 2) layer-0 input transform: xg = pooled @ Wih0^T + bih0 + bhh0
    gemm_xg<<<NF/16, 256>>>(pooled, Wih0, bih0, bhh0, xg, CC);

    // 3) zero h buffers + barrier state
    zero_init<<<(2*BB*HID + 255)/256, 256>>>(h0buf, h1buf);

    // 4) fused 2-layer pipelined recurrence at 128 blocks (257 rounds)
    lstm_fused128<<<LSTM_BLOCKS, 256, FUSED_SMEM_BYTES>>>(
        xg, Whh0, Wih1, Whh1, bih1, bhh1, slen, h0buf, h1buf, hlast);

    // 5) classifier
    final_kernel<<<1, 256>>>(hlast, clfw, clfb, out);
}